// round 1
// baseline (speedup 1.0000x reference)
#include <cuda_runtime.h>
#include <cstdint>

#define D_MODEL 1024
#define N_HEADS 16
#define HEAD_DIM 64
#define BATCH 2
#define SEQ 2048
#define M_TOT (BATCH*SEQ)   // 4096

// ---------------- scratch (device globals: no runtime allocation) ----------
__device__ float g_q[(size_t)M_TOT * D_MODEL];
__device__ float g_k[(size_t)M_TOT * D_MODEL];
__device__ float g_v[(size_t)M_TOT * D_MODEL];

// ---------------- helpers --------------------------------------------------
__device__ __forceinline__ unsigned f2tf(float x){
    unsigned r; asm("cvt.rna.tf32.f32 %0, %1;" : "=r"(r) : "f"(x)); return r;
}

__device__ __forceinline__ void mma_tf32(float* d, const unsigned* a, const unsigned* b){
    asm volatile(
        "mma.sync.aligned.m16n8k8.row.col.f32.tf32.tf32.f32 "
        "{%0,%1,%2,%3},{%4,%5,%6,%7},{%8,%9},{%0,%1,%2,%3};"
        : "+f"(d[0]), "+f"(d[1]), "+f"(d[2]), "+f"(d[3])
        : "r"(a[0]), "r"(a[1]), "r"(a[2]), "r"(a[3]), "r"(b[0]), "r"(b[1]));
}

__device__ __forceinline__ void cp_async16(void* sptr, const void* gptr){
    unsigned sa = (unsigned)__cvta_generic_to_shared(sptr);
    asm volatile("cp.async.cg.shared.global [%0], [%1], 16;" :: "r"(sa), "l"(gptr) : "memory");
}

// ===========================================================================
// QKV projection:  dst[b,n,s,h] = (X @ W + bias) (* 1/8 for Q)
// Tiles: BM=128, BN=128, BK=16, 256 threads (8 warps in 4x2), tf32 mma.
// ===========================================================================
#define G_BM 128
#define G_BN 128
#define G_BK 16
#define ASTR 20     // As[m][k] row stride (bank-conflict-free for A-frag reads)
#define BSTR 136    // Bs[k][n] row stride (bank-conflict-free for B-frag reads)
#define KTILES (D_MODEL/G_BK)   // 64

__global__ void __launch_bounds__(256) qkv_kernel(
    const float* __restrict__ from_t, const float* __restrict__ to_t,
    const float* __restrict__ Wq, const float* __restrict__ bq,
    const float* __restrict__ Wk, const float* __restrict__ bk,
    const float* __restrict__ Wv, const float* __restrict__ bv)
{
    __shared__ unsigned As[2][G_BM*ASTR];
    __shared__ unsigned Bs[2][G_BK*BSTR];

    const int z = blockIdx.z;
    const float* X    = (z==0) ? from_t : to_t;
    const float* W    = (z==0) ? Wq : (z==1 ? Wk : Wv);
    const float* bias = (z==0) ? bq : (z==1 ? bk : bv);
    float*       dst  = (z==0) ? g_q : (z==1 ? g_k : g_v);
    const float scale = (z==0) ? 0.125f : 1.0f;   // fold 1/sqrt(64) into Q

    const int m0 = blockIdx.x*G_BM, n0 = blockIdx.y*G_BN;
    const int tid  = threadIdx.x;
    const int warp = tid>>5, lane = tid&31;
    const int wm = warp>>1, wn = warp&1;     // warp tile: 32 rows x 64 cols
    const int g = lane>>2, tg = lane&3;

    float4 aR[2], bR[2];

    // --- staging helpers (macros keep regs/indices simple) ---
#define LDG_TILE(kt) do { \
        _Pragma("unroll") \
        for (int s=0; s<2; s++){ \
            int ia = tid + s*256; \
            aR[s] = *(const float4*)(X + (size_t)(m0 + (ia>>2))*D_MODEL + (kt)*G_BK + (ia&3)*4); \
            bR[s] = *(const float4*)(W + (size_t)((kt)*G_BK + (ia>>5))*D_MODEL + n0 + (ia&31)*4); \
        } } while(0)

#define STS_TILE(bufi) do { \
        _Pragma("unroll") \
        for (int s=0; s<2; s++){ \
            int ia = tid + s*256; \
            unsigned* pa = &As[bufi][(ia>>2)*ASTR + (ia&3)*4]; \
            pa[0]=f2tf(aR[s].x); pa[1]=f2tf(aR[s].y); pa[2]=f2tf(aR[s].z); pa[3]=f2tf(aR[s].w); \
            unsigned* pb = &Bs[bufi][(ia>>5)*BSTR + (ia&31)*4]; \
            pb[0]=f2tf(bR[s].x); pb[1]=f2tf(bR[s].y); pb[2]=f2tf(bR[s].z); pb[3]=f2tf(bR[s].w); \
        } } while(0)

    float acc[2][8][4];
    #pragma unroll
    for (int i=0;i<2;i++)
        #pragma unroll
        for (int j=0;j<8;j++)
            #pragma unroll
            for (int c=0;c<4;c++) acc[i][j][c]=0.f;

    LDG_TILE(0); STS_TILE(0);
    LDG_TILE(1);
    __syncthreads();

    for (int kt=0; kt<KTILES; kt++){
        const int buf = kt&1;
        if (kt+1 < KTILES) STS_TILE(buf^1);   // regs hold tile kt+1
        if (kt+2 < KTILES) LDG_TILE(kt+2);

        #pragma unroll
        for (int ks=0; ks<2; ks++){
            const int k = ks*8;
            unsigned a[2][4], b[8][2];
            #pragma unroll
            for (int mf=0; mf<2; mf++){
                int r = wm*32 + mf*16 + g;
                a[mf][0]=As[buf][r*ASTR + k+tg];
                a[mf][1]=As[buf][(r+8)*ASTR + k+tg];
                a[mf][2]=As[buf][r*ASTR + k+tg+4];
                a[mf][3]=As[buf][(r+8)*ASTR + k+tg+4];
            }
            #pragma unroll
            for (int nf=0; nf<8; nf++){
                int c = wn*64 + nf*8 + g;
                b[nf][0]=Bs[buf][(k+tg)*BSTR + c];
                b[nf][1]=Bs[buf][(k+tg+4)*BSTR + c];
            }
            #pragma unroll
            for (int mf=0; mf<2; mf++)
                #pragma unroll
                for (int nf=0; nf<8; nf++)
                    mma_tf32(acc[mf][nf], a[mf], b[nf]);
        }
        __syncthreads();
    }

    // epilogue: bias + scale, write to [b, head, s, h] scratch
    #pragma unroll
    for (int mf=0; mf<2; mf++){
        #pragma unroll
        for (int nf=0; nf<8; nf++){
            int m = m0 + wm*32 + mf*16 + g;
            int c = n0 + wn*64 + nf*8 + 2*tg;
            float b0 = bias[c], b1 = bias[c+1];
            #pragma unroll
            for (int half=0; half<2; half++){
                int mm = m + half*8;
                int bi = mm >> 11, ss = mm & (SEQ-1);
                int hd = c >> 6,  hh = c & (HEAD_DIM-1);
                float2 v;
                v.x = (acc[mf][nf][2*half]   + b0)*scale;
                v.y = (acc[mf][nf][2*half+1] + b1)*scale;
                *(float2*)(dst + ((size_t)(bi*N_HEADS + hd)*SEQ + ss)*HEAD_DIM + hh) = v;
            }
        }
    }
#undef LDG_TILE
#undef STS_TILE
}

// ===========================================================================
// Flash attention: per (b,head) x F-tile(128). T-tile 64, cp.async double buf.
// 128 threads (4 warps); each warp owns 32 F-rows.
// ===========================================================================
#define FT 128
#define TT 64
#define NIT (SEQ/TT)     // 32
#define QSTR 68
#define KSTR 68
#define VSTR 72
#define PSTR 68
#define SMEM_Q (FT*QSTR)        // uint (tf32)
#define SMEM_K (TT*KSTR)        // float
#define SMEM_V (TT*VSTR)        // float
#define SMEM_P (4*32*PSTR)      // uint (tf32), per-warp
#define ATTN_SMEM_BYTES ((SMEM_Q + 2*SMEM_K + 2*SMEM_V + SMEM_P)*4)

__global__ void __launch_bounds__(128, 1) attn_kernel(
    const int* __restrict__ mask, float* __restrict__ out)
{
    extern __shared__ unsigned char smraw[];
    unsigned* Qs = (unsigned*)smraw;                 // [FT][QSTR]
    float*    Kb = (float*)(Qs + SMEM_Q);            // [2][TT][KSTR]
    float*    Vb = Kb + 2*SMEM_K;                    // [2][TT][VSTR]
    unsigned* Ps = (unsigned*)(Vb + 2*SMEM_V);       // [4][32][PSTR]

    const int ft = blockIdx.x, bn = blockIdx.y;
    const int b = bn >> 4, head = bn & 15;
    const int tid = threadIdx.x;
    const int w = tid>>5, lane = tid&31, g = lane>>2, tg = lane&3;
    const int f0 = ft*FT;

    const float* qp = g_q + (size_t)bn*SEQ*HEAD_DIM;
    const float* kp = g_k + (size_t)bn*SEQ*HEAD_DIM;
    const float* vp = g_v + (size_t)bn*SEQ*HEAD_DIM;
    const int*   mp = mask + (size_t)b*SEQ*SEQ;

    // stage Q (already scaled by 1/8) -> tf32 smem
    #pragma unroll
    for (int s=0;s<16;s++){
        int i = tid + s*128;
        int row = i>>4, c4 = i&15;
        float4 v = *(const float4*)(qp + (size_t)(f0+row)*HEAD_DIM + c4*4);
        unsigned* p = &Qs[row*QSTR + c4*4];
        p[0]=f2tf(v.x); p[1]=f2tf(v.y); p[2]=f2tf(v.z); p[3]=f2tf(v.w);
    }

#define PREFETCH(it_, bufi) do { \
        const float* kpn = kp + (size_t)(it_)*TT*HEAD_DIM; \
        const float* vpn = vp + (size_t)(it_)*TT*HEAD_DIM; \
        _Pragma("unroll") \
        for (int s=0;s<8;s++){ \
            int i = tid + s*128; \
            int row = i>>4, c4 = i&15; \
            cp_async16(&Kb[(bufi)*SMEM_K + row*KSTR + c4*4], kpn + (size_t)row*HEAD_DIM + c4*4); \
            cp_async16(&Vb[(bufi)*SMEM_V + row*VSTR + c4*4], vpn + (size_t)row*HEAD_DIM + c4*4); \
        } \
        asm volatile("cp.async.commit_group;" ::: "memory"); \
    } while(0)

    PREFETCH(0, 0);

    float oacc[2][8][4];
    #pragma unroll
    for (int i=0;i<2;i++)
        #pragma unroll
        for (int j=0;j<8;j++)
            #pragma unroll
            for (int c=0;c<4;c++) oacc[i][j][c]=0.f;

    float mstate[4], lstate[4];
    #pragma unroll
    for (int r=0;r<4;r++){ mstate[r] = -1e30f; lstate[r] = 0.f; }

    for (int it=0; it<NIT; it++){
        if (it+1 < NIT){
            PREFETCH(it+1, (it+1)&1);
            asm volatile("cp.async.wait_group 1;" ::: "memory");
        } else {
            asm volatile("cp.async.wait_group 0;" ::: "memory");
        }
        __syncthreads();

        const float* KB = Kb + (it&1)*SMEM_K;
        const float* VB = Vb + (it&1)*SMEM_V;

        // ---- S = Q K^T (scaled Q already), 32x64 per warp ----
        float sacc[2][8][4];
        #pragma unroll
        for (int i=0;i<2;i++)
            #pragma unroll
            for (int j=0;j<8;j++)
                #pragma unroll
                for (int c=0;c<4;c++) sacc[i][j][c]=0.f;

        #pragma unroll
        for (int ks=0; ks<8; ks++){
            unsigned a[2][4], bb[8][2];
            #pragma unroll
            for (int mf=0; mf<2; mf++){
                int r = w*32 + mf*16 + g;
                a[mf][0]=Qs[r*QSTR + ks*8+tg];
                a[mf][1]=Qs[(r+8)*QSTR + ks*8+tg];
                a[mf][2]=Qs[r*QSTR + ks*8+tg+4];
                a[mf][3]=Qs[(r+8)*QSTR + ks*8+tg+4];
            }
            #pragma unroll
            for (int nf=0; nf<8; nf++){
                int t = nf*8 + g;
                bb[nf][0]=f2tf(KB[t*KSTR + ks*8+tg]);
                bb[nf][1]=f2tf(KB[t*KSTR + ks*8+tg+4]);
            }
            #pragma unroll
            for (int mf=0; mf<2; mf++)
                #pragma unroll
                for (int nf=0; nf<8; nf++)
                    mma_tf32(sacc[mf][nf], a[mf], bb[nf]);
        }

        // ---- additive mask ----
        const int t0 = it*TT;
        #pragma unroll
        for (int mf=0; mf<2; mf++){
            #pragma unroll
            for (int half=0; half<2; half++){
                int frow = f0 + w*32 + mf*16 + g + half*8;
                const int* mrow = mp + (size_t)frow*SEQ + t0;
                #pragma unroll
                for (int nf=0; nf<8; nf++){
                    int2 mv = __ldg((const int2*)(mrow + nf*8 + 2*tg));
                    sacc[mf][nf][2*half]   += (1.0f - (float)mv.x) * -10000.0f;
                    sacc[mf][nf][2*half+1] += (1.0f - (float)mv.y) * -10000.0f;
                }
            }
        }

        // ---- online softmax ----
        #pragma unroll
        for (int mf=0; mf<2; mf++){
            #pragma unroll
            for (int half=0; half<2; half++){
                const int rid = mf*2 + half;
                float mx = -1e30f;
                #pragma unroll
                for (int nf=0; nf<8; nf++)
                    mx = fmaxf(mx, fmaxf(sacc[mf][nf][2*half], sacc[mf][nf][2*half+1]));
                mx = fmaxf(mx, __shfl_xor_sync(0xffffffffu, mx, 1));
                mx = fmaxf(mx, __shfl_xor_sync(0xffffffffu, mx, 2));
                float mnew  = fmaxf(mstate[rid], mx);
                float alpha = __expf(mstate[rid] - mnew);
                float rsum = 0.f;
                #pragma unroll
                for (int nf=0; nf<8; nf++){
                    float p0 = __expf(sacc[mf][nf][2*half]   - mnew);
                    float p1 = __expf(sacc[mf][nf][2*half+1] - mnew);
                    sacc[mf][nf][2*half] = p0; sacc[mf][nf][2*half+1] = p1;
                    rsum += p0 + p1;
                }
                rsum += __shfl_xor_sync(0xffffffffu, rsum, 1);
                rsum += __shfl_xor_sync(0xffffffffu, rsum, 2);
                lstate[rid] = lstate[rid]*alpha + rsum;
                mstate[rid] = mnew;
                #pragma unroll
                for (int nf=0; nf<8; nf++){
                    oacc[mf][nf][2*half]   *= alpha;
                    oacc[mf][nf][2*half+1] *= alpha;
                }
            }
        }

        // ---- write P (tf32) to per-warp smem ----
        unsigned* Pw = Ps + w*32*PSTR;
        __syncwarp();
        #pragma unroll
        for (int mf=0; mf<2; mf++){
            #pragma unroll
            for (int half=0; half<2; half++){
                int r = mf*16 + g + half*8;
                #pragma unroll
                for (int nf=0; nf<8; nf++){
                    uint2 pv;
                    pv.x = f2tf(sacc[mf][nf][2*half]);
                    pv.y = f2tf(sacc[mf][nf][2*half+1]);
                    *(uint2*)(Pw + r*PSTR + nf*8 + 2*tg) = pv;
                }
            }
        }
        __syncwarp();

        // ---- O += P V ----
        #pragma unroll
        for (int ks=0; ks<8; ks++){
            unsigned a[2][4], bb[8][2];
            #pragma unroll
            for (int mf=0; mf<2; mf++){
                int r = mf*16 + g;
                a[mf][0]=Pw[r*PSTR + ks*8+tg];
                a[mf][1]=Pw[(r+8)*PSTR + ks*8+tg];
                a[mf][2]=Pw[r*PSTR + ks*8+tg+4];
                a[mf][3]=Pw[(r+8)*PSTR + ks*8+tg+4];
            }
            #pragma unroll
            for (int nf=0; nf<8; nf++){
                bb[nf][0]=f2tf(VB[(ks*8+tg)*VSTR + nf*8+g]);
                bb[nf][1]=f2tf(VB[(ks*8+tg+4)*VSTR + nf*8+g]);
            }
            #pragma unroll
            for (int mf=0; mf<2; mf++)
                #pragma unroll
                for (int nf=0; nf<8; nf++)
                    mma_tf32(oacc[mf][nf], a[mf], bb[nf]);
        }
        __syncthreads();   // protect K/V/P buffers before next overwrite
    }

    // ---- finalize: O /= l, write [B, F, N*H] ----
    float inv[4];
    #pragma unroll
    for (int r=0;r<4;r++) inv[r] = (lstate[r] > 0.f) ? 1.0f/lstate[r] : 0.f;

    #pragma unroll
    for (int mf=0; mf<2; mf++){
        #pragma unroll
        for (int half=0; half<2; half++){
            const int rid = mf*2 + half;
            int frow = f0 + w*32 + mf*16 + g + half*8;
            #pragma unroll
            for (int nf=0; nf<8; nf++){
                int col = head*HEAD_DIM + nf*8 + 2*tg;
                float2 o;
                o.x = oacc[mf][nf][2*half]   * inv[rid];
                o.y = oacc[mf][nf][2*half+1] * inv[rid];
                *(float2*)(out + ((size_t)b*SEQ + frow)*D_MODEL + col) = o;
            }
        }
    }
#undef PREFETCH
}

// ===========================================================================
extern "C" void kernel_launch(void* const* d_in, const int* in_sizes, int n_in,
                              void* d_out, int out_size)
{
    (void)in_sizes; (void)n_in; (void)out_size;
    const float* from_t = (const float*)d_in[0];
    const float* to_t   = (const float*)d_in[1];
    const int*   mask   = (const int*)  d_in[2];
    const float* Wq = (const float*)d_in[3];
    const float* bq = (const float*)d_in[4];
    const float* Wk = (const float*)d_in[5];
    const float* bk = (const float*)d_in[6];
    const float* Wv = (const float*)d_in[7];
    const float* bv = (const float*)d_in[8];
    float* out = (float*)d_out;

    dim3 gg(M_TOT/G_BM, D_MODEL/G_BN, 3);
    qkv_kernel<<<gg, 256>>>(from_t, to_t, Wq, bq, Wk, bk, Wv, bv);

    cudaFuncSetAttribute(attn_kernel, cudaFuncAttributeMaxDynamicSharedMemorySize,
                         ATTN_SMEM_BYTES);
    attn_kernel<<<dim3(SEQ/FT, BATCH*N_HEADS), 128, ATTN_SMEM_BYTES>>>(mask, out);
}

// round 4
// speedup vs baseline: 1.0380x; 1.0380x over previous
#include <cuda_runtime.h>
#include <cstdint>

#define D_MODEL 1024
#define N_HEADS 16
#define HEAD_DIM 64
#define BATCH 2
#define SEQ 2048
#define M_TOT (BATCH*SEQ)   // 4096

// ---------------- scratch (device globals: no runtime allocation) ----------
// Stored as PRE-CONVERTED tf32 bit patterns (uint32) so the attention kernel
// never needs cvt instructions on Q/K/V fragments.
__device__ unsigned g_q[(size_t)M_TOT * D_MODEL];
__device__ unsigned g_k[(size_t)M_TOT * D_MODEL];
__device__ unsigned g_v[(size_t)M_TOT * D_MODEL];

// ---------------- helpers --------------------------------------------------
__device__ __forceinline__ unsigned f2tf(float x){
    unsigned r; asm("cvt.rna.tf32.f32 %0, %1;" : "=r"(r) : "f"(x)); return r;
}

__device__ __forceinline__ void mma_tf32(float* d, const unsigned* a, const unsigned* b){
    asm volatile(
        "mma.sync.aligned.m16n8k8.row.col.f32.tf32.tf32.f32 "
        "{%0,%1,%2,%3},{%4,%5,%6,%7},{%8,%9},{%0,%1,%2,%3};"
        : "+f"(d[0]), "+f"(d[1]), "+f"(d[2]), "+f"(d[3])
        : "r"(a[0]), "r"(a[1]), "r"(a[2]), "r"(a[3]), "r"(b[0]), "r"(b[1]));
}

__device__ __forceinline__ void cp_async16(void* sptr, const void* gptr){
    unsigned sa = (unsigned)__cvta_generic_to_shared(sptr);
    asm volatile("cp.async.cg.shared.global [%0], [%1], 16;" :: "r"(sa), "l"(gptr) : "memory");
}

// ===========================================================================
// QKV projection:  dst[b,n,s,h] = tf32( (X @ W + bias) (* 1/8 for Q) )
// Tiles: BM=128, BN=128, BK=16, 256 threads (8 warps in 4x2), tf32 mma.
// ===========================================================================
#define G_BM 128
#define G_BN 128
#define G_BK 16
#define ASTR 20     // As[m][k] row stride (bank-conflict-free for A-frag reads)
#define BSTR 136    // Bs[k][n] row stride (bank-conflict-free for B-frag reads)
#define KTILES (D_MODEL/G_BK)   // 64

__global__ void __launch_bounds__(256, 2) qkv_kernel(
    const float* __restrict__ from_t, const float* __restrict__ to_t,
    const float* __restrict__ Wq, const float* __restrict__ bq,
    const float* __restrict__ Wk, const float* __restrict__ bk,
    const float* __restrict__ Wv, const float* __restrict__ bv)
{
    __shared__ unsigned As[2][G_BM*ASTR];
    __shared__ unsigned Bs[2][G_BK*BSTR];

    const int z = blockIdx.z;
    const float* X    = (z==0) ? from_t : to_t;
    const float* W    = (z==0) ? Wq : (z==1 ? Wk : Wv);
    const float* bias = (z==0) ? bq : (z==1 ? bk : bv);
    unsigned*    dst  = (z==0) ? g_q : (z==1 ? g_k : g_v);
    const float scale = (z==0) ? 0.125f : 1.0f;   // fold 1/sqrt(64) into Q

    const int m0 = blockIdx.x*G_BM, n0 = blockIdx.y*G_BN;
    const int tid  = threadIdx.x;
    const int warp = tid>>5, lane = tid&31;
    const int wm = warp>>1, wn = warp&1;     // warp tile: 32 rows x 64 cols
    const int g = lane>>2, tg = lane&3;

    float4 aR[2], bR[2];

#define LDG_TILE(kt) do { \
        _Pragma("unroll") \
        for (int s=0; s<2; s++){ \
            int ia = tid + s*256; \
            aR[s] = *(const float4*)(X + (size_t)(m0 + (ia>>2))*D_MODEL + (kt)*G_BK + (ia&3)*4); \
            bR[s] = *(const float4*)(W + (size_t)((kt)*G_BK + (ia>>5))*D_MODEL + n0 + (ia&31)*4); \
        } } while(0)

#define STS_TILE(bufi) do { \
        _Pragma("unroll") \
        for (int s=0; s<2; s++){ \
            int ia = tid + s*256; \
            unsigned* pa = &As[bufi][(ia>>2)*ASTR + (ia&3)*4]; \
            pa[0]=f2tf(aR[s].x); pa[1]=f2tf(aR[s].y); pa[2]=f2tf(aR[s].z); pa[3]=f2tf(aR[s].w); \
            unsigned* pb = &Bs[bufi][(ia>>5)*BSTR + (ia&31)*4]; \
            pb[0]=f2tf(bR[s].x); pb[1]=f2tf(bR[s].y); pb[2]=f2tf(bR[s].z); pb[3]=f2tf(bR[s].w); \
        } } while(0)

    float acc[2][8][4];
    #pragma unroll
    for (int i=0;i<2;i++)
        #pragma unroll
        for (int j=0;j<8;j++)
            #pragma unroll
            for (int c=0;c<4;c++) acc[i][j][c]=0.f;

    LDG_TILE(0); STS_TILE(0);
    LDG_TILE(1);
    __syncthreads();

    for (int kt=0; kt<KTILES; kt++){
        const int buf = kt&1;
        if (kt+1 < KTILES) STS_TILE(buf^1);   // regs hold tile kt+1
        if (kt+2 < KTILES) LDG_TILE(kt+2);

        #pragma unroll
        for (int ks=0; ks<2; ks++){
            const int k = ks*8;
            unsigned a[2][4], b[8][2];
            #pragma unroll
            for (int mf=0; mf<2; mf++){
                int r = wm*32 + mf*16 + g;
                a[mf][0]=As[buf][r*ASTR + k+tg];
                a[mf][1]=As[buf][(r+8)*ASTR + k+tg];
                a[mf][2]=As[buf][r*ASTR + k+tg+4];
                a[mf][3]=As[buf][(r+8)*ASTR + k+tg+4];
            }
            #pragma unroll
            for (int nf=0; nf<8; nf++){
                int c = wn*64 + nf*8 + g;
                b[nf][0]=Bs[buf][(k+tg)*BSTR + c];
                b[nf][1]=Bs[buf][(k+tg+4)*BSTR + c];
            }
            #pragma unroll
            for (int mf=0; mf<2; mf++)
                #pragma unroll
                for (int nf=0; nf<8; nf++)
                    mma_tf32(acc[mf][nf], a[mf], b[nf]);
        }
        __syncthreads();
    }

    // epilogue: bias + scale, convert to tf32 bits, write [b, head, s, h]
    #pragma unroll
    for (int mf=0; mf<2; mf++){
        #pragma unroll
        for (int nf=0; nf<8; nf++){
            int m = m0 + wm*32 + mf*16 + g;
            int c = n0 + wn*64 + nf*8 + 2*tg;
            float b0 = bias[c], b1 = bias[c+1];
            #pragma unroll
            for (int half=0; half<2; half++){
                int mm = m + half*8;
                int bi = mm >> 11, ss = mm & (SEQ-1);
                int hd = c >> 6,  hh = c & (HEAD_DIM-1);
                uint2 v;
                v.x = f2tf((acc[mf][nf][2*half]   + b0)*scale);
                v.y = f2tf((acc[mf][nf][2*half+1] + b1)*scale);
                *(uint2*)(dst + ((size_t)(bi*N_HEADS + hd)*SEQ + ss)*HEAD_DIM + hh) = v;
            }
        }
    }
#undef LDG_TILE
#undef STS_TILE
}

// ===========================================================================
// Flash attention: per (b,head) x F-tile(128). T-tile 64, cp.async double buf.
// 256 threads (8 warps); each warp owns 16 F-rows. Q fragments live in
// registers; the Q smem region is reused as the per-warp P buffer.
// ===========================================================================
#define FT 128
#define TT 64
#define NIT (SEQ/TT)     // 32
#define QSTR 68
#define KSTR 68
#define VSTR 72
#define SMEM_Q (FT*QSTR)        // uint (tf32); reused as P after Q-frag preload
#define SMEM_K (TT*KSTR)        // uint (tf32)
#define SMEM_V (TT*VSTR)        // uint (tf32)
#define ATTN_SMEM_BYTES ((SMEM_Q + 2*SMEM_K + 2*SMEM_V)*4)   // 106,496 B

__global__ void __launch_bounds__(256, 1) attn_kernel(
    const int* __restrict__ mask, float* __restrict__ out)
{
    extern __shared__ unsigned char smraw[];
    unsigned* Qs = (unsigned*)smraw;                 // [FT][QSTR] -> later P
    unsigned* Kb = Qs + SMEM_Q;                      // [2][TT][KSTR]
    unsigned* Vb = Kb + 2*SMEM_K;                    // [2][TT][VSTR]

    const int ft = blockIdx.x, bn = blockIdx.y;
    const int b = bn >> 4, head = bn & 15;
    const int tid = threadIdx.x;
    const int w = tid>>5, lane = tid&31, g = lane>>2, tg = lane&3;
    const int f0 = ft*FT;

    const unsigned* qp = g_q + (size_t)bn*SEQ*HEAD_DIM;
    const unsigned* kp = g_k + (size_t)bn*SEQ*HEAD_DIM;
    const unsigned* vp = g_v + (size_t)bn*SEQ*HEAD_DIM;
    const int*      mp = mask + (size_t)b*SEQ*SEQ;

    // stage Q (pre-scaled, pre-converted tf32) into smem
    #pragma unroll
    for (int s=0;s<8;s++){
        int i = tid + s*256;
        int row = i>>4, c4 = i&15;
        uint4 v = *(const uint4*)(qp + (size_t)(f0+row)*HEAD_DIM + c4*4);
        *(uint4*)&Qs[row*QSTR + c4*4] = v;           // 272B rows keep 16B align
    }
    __syncthreads();

    // preload Q fragments into registers (each warp reads only its own rows)
    unsigned qa[8][4];
    {
        int r = w*16 + g;
        #pragma unroll
        for (int ks=0; ks<8; ks++){
            qa[ks][0]=Qs[r*QSTR     + ks*8+tg];
            qa[ks][1]=Qs[(r+8)*QSTR + ks*8+tg];
            qa[ks][2]=Qs[r*QSTR     + ks*8+tg+4];
            qa[ks][3]=Qs[(r+8)*QSTR + ks*8+tg+4];
        }
    }
    unsigned* Pw = Qs + (w*16)*QSTR;   // per-warp P region overlays this warp's Q rows

#define PREFETCH(it_, bufi) do { \
        const unsigned* kpn = kp + (size_t)(it_)*TT*HEAD_DIM; \
        const unsigned* vpn = vp + (size_t)(it_)*TT*HEAD_DIM; \
        _Pragma("unroll") \
        for (int s=0;s<4;s++){ \
            int i = tid + s*256; \
            int row = i>>4, c4 = i&15; \
            cp_async16(&Kb[(bufi)*SMEM_K + row*KSTR + c4*4], kpn + (size_t)row*HEAD_DIM + c4*4); \
            cp_async16(&Vb[(bufi)*SMEM_V + row*VSTR + c4*4], vpn + (size_t)row*HEAD_DIM + c4*4); \
        } \
        asm volatile("cp.async.commit_group;" ::: "memory"); \
    } while(0)

    PREFETCH(0, 0);

    float oacc[8][4];
    #pragma unroll
    for (int j=0;j<8;j++)
        #pragma unroll
        for (int c=0;c<4;c++) oacc[j][c]=0.f;

    float mstate[2] = {-1e30f, -1e30f};
    float lstate[2] = {0.f, 0.f};

    for (int it=0; it<NIT; it++){
        if (it+1 < NIT){
            PREFETCH(it+1, (it+1)&1);
            asm volatile("cp.async.wait_group 1;" ::: "memory");
        } else {
            asm volatile("cp.async.wait_group 0;" ::: "memory");
        }
        __syncthreads();

        const unsigned* KB = Kb + (it&1)*SMEM_K;
        const unsigned* VB = Vb + (it&1)*SMEM_V;

        // ---- S = Q K^T (Q pre-scaled), 16x64 per warp ----
        float sacc[8][4];
        #pragma unroll
        for (int j=0;j<8;j++)
            #pragma unroll
            for (int c=0;c<4;c++) sacc[j][c]=0.f;

        #pragma unroll
        for (int ks=0; ks<8; ks++){
            unsigned bb[8][2];
            #pragma unroll
            for (int nf=0; nf<8; nf++){
                int t = nf*8 + g;
                bb[nf][0]=KB[t*KSTR + ks*8+tg];
                bb[nf][1]=KB[t*KSTR + ks*8+tg+4];
            }
            #pragma unroll
            for (int nf=0; nf<8; nf++)
                mma_tf32(sacc[nf], qa[ks], bb[nf]);
        }

        // ---- additive mask ----
        const int t0 = it*TT;
        #pragma unroll
        for (int half=0; half<2; half++){
            int frow = f0 + w*16 + g + half*8;
            const int* mrow = mp + (size_t)frow*SEQ + t0;
            #pragma unroll
            for (int nf=0; nf<8; nf++){
                int2 mv = __ldg((const int2*)(mrow + nf*8 + 2*tg));
                sacc[nf][2*half]   += (1.0f - (float)mv.x) * -10000.0f;
                sacc[nf][2*half+1] += (1.0f - (float)mv.y) * -10000.0f;
            }
        }

        // ---- online softmax (2 rows per thread) ----
        #pragma unroll
        for (int half=0; half<2; half++){
            float mx = -1e30f;
            #pragma unroll
            for (int nf=0; nf<8; nf++)
                mx = fmaxf(mx, fmaxf(sacc[nf][2*half], sacc[nf][2*half+1]));
            mx = fmaxf(mx, __shfl_xor_sync(0xffffffffu, mx, 1));
            mx = fmaxf(mx, __shfl_xor_sync(0xffffffffu, mx, 2));
            float mnew  = fmaxf(mstate[half], mx);
            float alpha = __expf(mstate[half] - mnew);
            float rsum = 0.f;
            #pragma unroll
            for (int nf=0; nf<8; nf++){
                float p0 = __expf(sacc[nf][2*half]   - mnew);
                float p1 = __expf(sacc[nf][2*half+1] - mnew);
                sacc[nf][2*half] = p0; sacc[nf][2*half+1] = p1;
                rsum += p0 + p1;
            }
            rsum += __shfl_xor_sync(0xffffffffu, rsum, 1);
            rsum += __shfl_xor_sync(0xffffffffu, rsum, 2);
            lstate[half] = lstate[half]*alpha + rsum;
            mstate[half] = mnew;
            #pragma unroll
            for (int nf=0; nf<8; nf++){
                oacc[nf][2*half]   *= alpha;
                oacc[nf][2*half+1] *= alpha;
            }
        }

        // ---- write P (tf32) to per-warp smem (own rows only) ----
        __syncwarp();
        #pragma unroll
        for (int half=0; half<2; half++){
            int r = g + half*8;
            #pragma unroll
            for (int nf=0; nf<8; nf++){
                uint2 pv;
                pv.x = f2tf(sacc[nf][2*half]);
                pv.y = f2tf(sacc[nf][2*half+1]);
                *(uint2*)(Pw + r*QSTR + nf*8 + 2*tg) = pv;
            }
        }
        __syncwarp();

        // ---- O += P V ----
        #pragma unroll
        for (int ks=0; ks<8; ks++){
            unsigned a[4], bb[8][2];
            a[0]=Pw[g*QSTR     + ks*8+tg];
            a[1]=Pw[(g+8)*QSTR + ks*8+tg];
            a[2]=Pw[g*QSTR     + ks*8+tg+4];
            a[3]=Pw[(g+8)*QSTR + ks*8+tg+4];
            #pragma unroll
            for (int nf=0; nf<8; nf++){
                bb[nf][0]=VB[(ks*8+tg)*VSTR   + nf*8+g];
                bb[nf][1]=VB[(ks*8+tg+4)*VSTR + nf*8+g];
            }
            #pragma unroll
            for (int nf=0; nf<8; nf++)
                mma_tf32(oacc[nf], a, bb[nf]);
        }
        __syncthreads();   // protect K/V buffers before next overwrite
    }

    // ---- finalize: O /= l, write [B, F, N*H] ----
    float inv[2];
    #pragma unroll
    for (int r=0;r<2;r++) inv[r] = (lstate[r] > 0.f) ? 1.0f/lstate[r] : 0.f;

    #pragma unroll
    for (int half=0; half<2; half++){
        int frow = f0 + w*16 + g + half*8;
        #pragma unroll
        for (int nf=0; nf<8; nf++){
            int col = head*HEAD_DIM + nf*8 + 2*tg;
            float2 o;
            o.x = oacc[nf][2*half]   * inv[half];
            o.y = oacc[nf][2*half+1] * inv[half];
            *(float2*)(out + ((size_t)b*SEQ + frow)*D_MODEL + col) = o;
        }
    }
#undef PREFETCH
}

// ===========================================================================
extern "C" void kernel_launch(void* const* d_in, const int* in_sizes, int n_in,
                              void* d_out, int out_size)
{
    (void)in_sizes; (void)n_in; (void)out_size;
    const float* from_t = (const float*)d_in[0];
    const float* to_t   = (const float*)d_in[1];
    const int*   mask   = (const int*)  d_in[2];
    const float* Wq = (const float*)d_in[3];
    const float* bq = (const float*)d_in[4];
    const float* Wk = (const float*)d_in[5];
    const float* bk = (const float*)d_in[6];
    const float* Wv = (const float*)d_in[7];
    const float* bv = (const float*)d_in[8];
    float* out = (float*)d_out;

    dim3 gg(M_TOT/G_BM, D_MODEL/G_BN, 3);
    qkv_kernel<<<gg, 256>>>(from_t, to_t, Wq, bq, Wk, bk, Wv, bv);

    cudaFuncSetAttribute(attn_kernel, cudaFuncAttributeMaxDynamicSharedMemorySize,
                         ATTN_SMEM_BYTES);
    attn_kernel<<<dim3(SEQ/FT, BATCH*N_HEADS), 256, ATTN_SMEM_BYTES>>>(mask, out);
}